// round 16
// baseline (speedup 1.0000x reference)
#include <cuda_runtime.h>
#include <cuda_bf16.h>

// ---------------------------------------------------------------------------
// FlattenedWindowMapping (outputs compared as float32)
// Layout: concat [flat2win[n_p] | win2flat[n] | idx_x[n] | idx_y[n]]
//
// Counting sort over (flag, batch, window) buckets (2^19 bins).
//   bin_x = b<<14 | wcx<<8 | wcy<<2 | wcz
//   bin_y = 1<<18 | b<<14 | wcy<<8 | wcx<<2 | wcz
//   element = ciw<<21 | i   (ciw 11 bits, i < 2^21)
//
// Pad-with-embedded-counter: each bin owns a 64B row [cnt, d0..d14].
// atomicAdd(row[0]) returns the slot AND pulls the line into LTS; the data
// write hits the SAME line -> ~1 unique random L2 line per orientation
// (vs 3 in the hist+offs+scatter pipeline).
//
// Pipeline (5 launches):
//  1. scatter    : coords pass; per orientation: atomic-slot + same-line
//                  write. Block 0 piggybacks batch_setup. >15/row -> ovf list.
//  2. scan_local : read+zero strided counters (L2-hot), local excl scan.
//  3. scan_tiles : one block scans 1024 tile totals.
//  4. window_sort: uint4 row loads + spill-free register Batcher-16,
//                  writes float idx_x/idx_y directly into d_out.
//  5. final_maps : flat2win + win2flat from batch tables; resets ovf.
// ---------------------------------------------------------------------------

#define MAXB  16
#define NMAX  2000000            // < 2^21 - 1
#define NBINS (1 << 19)
#define GROUPSZ 128

#define ROW_WORDS 16             // 64B row: [cnt, d0..d14]
#define ROW_SHIFT 4
#define ROW_DATA  15

#define S1_BLOCK 128
#define S1_ITEMS 4
#define SCAN_TILE  (S1_BLOCK * S1_ITEMS)          // 512
#define NTILES     (NBINS / SCAN_TILE)            // 1024
#define TILE_SHIFT 9

#define OVF_CAP 16384

__device__ int g_nb;
__device__ int g_bs[MAXB + 1];
__device__ int g_num[MAXB];
__device__ int g_nump[MAXB];
__device__ int g_bsp[MAXB + 1];
__device__ int g_bias[MAXB];

__device__ __align__(64) unsigned int g_pad[NBINS * ROW_WORDS];  // 32 MB
__device__ __align__(16) unsigned int g_offs[NBINS];
__device__ unsigned int g_tilesum[NTILES];
__device__ unsigned int g_tilebase[NTILES];
__device__ unsigned int g_ovf_cnt;               // zero-init; reset each run
__device__ uint2 g_ovf[OVF_CAP];

// --- Kernel 1: scatter with embedded counters (blk 0 = batch_setup) ---------
__global__ void scatter_kernel(const int* __restrict__ coords, int n, int ns,
                               const int* __restrict__ bsz_ptr) {
    if (blockIdx.x == 0) {
        __shared__ int nb_s;
        int t = threadIdx.x;
        if (t == 0) {
            int nb = bsz_ptr ? bsz_ptr[0] : 16;
            if (nb < 1) nb = 1;
            if (nb > MAXB) nb = MAXB;
            nb_s = nb;
            g_nb = nb;
        }
        __syncthreads();
        int nb = nb_s;
        if (t <= nb) {
            int lo = 0, hi = n;
            while (lo < hi) {
                int mid = (lo + hi) >> 1;
                if (coords[4 * mid] < t) lo = mid + 1; else hi = mid;
            }
            g_bs[t] = lo;
        }
        __syncthreads();
        if (t == 0) {
            int acc = 0;
            for (int b = 0; b < nb; b++) {
                int num  = g_bs[b + 1] - g_bs[b];
                int nump = ((num + GROUPSZ - 1) / GROUPSZ) * GROUPSZ;
                g_num[b]  = num;
                g_nump[b] = nump;
                g_bsp[b]  = acc;
                g_bias[b] = acc - g_bs[b];
                acc += nump;
            }
            g_bsp[nb] = acc;
        }
    }

    int i = blockIdx.x * blockDim.x + threadIdx.x;
    if (i >= ns) return;

    int4 c = reinterpret_cast<const int4*>(coords)[i];  // (b, z, y, x)
    unsigned int b = (unsigned int)c.x & 15u;
    unsigned int wcx = (unsigned int)(c.w >> 4), cix = (unsigned int)(c.w & 15);
    unsigned int wcy = (unsigned int)(c.z >> 4), ciy = (unsigned int)(c.z & 15);
    unsigned int wcz = (unsigned int)(c.y >> 3), ciz = (unsigned int)(c.y & 7);

    unsigned int bx = (b << 14) | (wcx << 8) | (wcy << 2) | wcz;
    unsigned int by = (1u << 18) | (b << 14) | (wcy << 8) | (wcx << 2) | wcz;

    unsigned int vx = (((cix << 7) | (ciy << 3) | ciz) << 21) | (unsigned int)i;
    unsigned int vy = (((ciy << 7) | (cix << 3) | ciz) << 21) | (unsigned int)i;

    unsigned int rowx = bx << ROW_SHIFT;
    unsigned int sx = atomicAdd(&g_pad[rowx], 1u);
    if (sx < ROW_DATA) {
        g_pad[rowx + 1u + sx] = vx;           // same 64B line as the atomic
    } else {
        unsigned int o = atomicAdd(&g_ovf_cnt, 1u);
        if (o < OVF_CAP) g_ovf[o] = make_uint2(bx, vx);
    }

    unsigned int rowy = by << ROW_SHIFT;
    unsigned int sy = atomicAdd(&g_pad[rowy], 1u);
    if (sy < ROW_DATA) {
        g_pad[rowy + 1u + sy] = vy;
    } else {
        unsigned int o = atomicAdd(&g_ovf_cnt, 1u);
        if (o < OVF_CAP) g_ovf[o] = make_uint2(by, vy);
    }
}

// --- Kernel 2: local excl scan of embedded counters (+ zero for replay) -----
__global__ void __launch_bounds__(S1_BLOCK)
scan_local_kernel() {
    __shared__ unsigned int s_warp[S1_BLOCK / 32];

    int tile = blockIdx.x;
    int t    = threadIdx.x;
    int wid  = t >> 5;
    int lane = t & 31;

    unsigned int base = (unsigned int)tile * SCAN_TILE
                      + (unsigned int)t * S1_ITEMS;

    unsigned int v0 = g_pad[(base + 0) << ROW_SHIFT];
    unsigned int v1 = g_pad[(base + 1) << ROW_SHIFT];
    unsigned int v2 = g_pad[(base + 2) << ROW_SHIFT];
    unsigned int v3 = g_pad[(base + 3) << ROW_SHIFT];
    g_pad[(base + 0) << ROW_SHIFT] = 0u;   // self-zero for graph replay
    g_pad[(base + 1) << ROW_SHIFT] = 0u;
    g_pad[(base + 2) << ROW_SHIFT] = 0u;
    g_pad[(base + 3) << ROW_SHIFT] = 0u;

    unsigned int T = v0 + v1 + v2 + v3;

    unsigned int inc = T;
    #pragma unroll
    for (int o = 1; o < 32; o <<= 1) {
        unsigned int u = __shfl_up_sync(0xffffffffu, inc, o);
        if (lane >= o) inc += u;
    }
    if (lane == 31) s_warp[wid] = inc;
    unsigned int thread_excl = inc - T;
    __syncthreads();

    if (wid == 0) {
        unsigned int w  = (lane < (S1_BLOCK / 32)) ? s_warp[lane] : 0u;
        unsigned int wi = w;
        #pragma unroll
        for (int o = 1; o < (S1_BLOCK / 32); o <<= 1) {
            unsigned int u = __shfl_up_sync(0xffffffffu, wi, o);
            if (lane >= o) wi += u;
        }
        if (lane < (S1_BLOCK / 32)) s_warp[lane] = wi - w;
        if (lane == (S1_BLOCK / 32) - 1) g_tilesum[tile] = wi;
    }
    __syncthreads();

    unsigned int off = s_warp[wid] + thread_excl;
    uint4 o1;
    o1.x = off;  off += v0;
    o1.y = off;  off += v1;
    o1.z = off;  off += v2;
    o1.w = off;
    *reinterpret_cast<uint4*>(&g_offs[base]) = o1;
}

// --- Kernel 3: single-block exclusive scan of 1024 tile totals --------------
__global__ void __launch_bounds__(NTILES)
scan_tiles_kernel() {
    __shared__ unsigned int s_warp[NTILES / 32];

    int t    = threadIdx.x;
    int wid  = t >> 5;
    int lane = t & 31;

    unsigned int T = g_tilesum[t];
    unsigned int inc = T;
    #pragma unroll
    for (int o = 1; o < 32; o <<= 1) {
        unsigned int u = __shfl_up_sync(0xffffffffu, inc, o);
        if (lane >= o) inc += u;
    }
    if (lane == 31) s_warp[wid] = inc;
    __syncthreads();

    if (wid == 0) {
        unsigned int w  = s_warp[lane];
        unsigned int wi = w;
        #pragma unroll
        for (int o = 1; o < 32; o <<= 1) {
            unsigned int u = __shfl_up_sync(0xffffffffu, wi, o);
            if (lane >= o) wi += u;
        }
        s_warp[lane] = wi - w;
    }
    __syncthreads();

    g_tilebase[t] = s_warp[wid] + (inc - T);
}

// --- Kernel 4: per-window register Batcher-16 sort from pad rows ------------
#define CE(a, b) { unsigned int lo = umin(v[a], v[b]); \
                   unsigned int hi = umax(v[a], v[b]); \
                   v[a] = lo; v[b] = hi; }

#define WTIER2 64
__global__ void __launch_bounds__(256, 2)
window_sort_kernel(float* __restrict__ out, int total) {
    int w = blockIdx.x * blockDim.x + threadIdx.x;
    if (w >= NBINS) return;

    unsigned int start = g_offs[w] + g_tilebase[w >> TILE_SHIFT];
    unsigned int end   = (w == NBINS - 1)
        ? (unsigned int)total
        : g_offs[w + 1] + g_tilebase[(w + 1) >> TILE_SHIFT];
    int cnt = (int)(end - start);
    if (cnt <= 0) return;

    const unsigned int M21  = (1u << 21) - 1u;
    const unsigned int SENT = 0xFFFFFFFFu;
    unsigned int rbase = (unsigned int)w << ROW_SHIFT;
    const uint4* row = reinterpret_cast<const uint4*>(&g_pad[rbase]);

    if (cnt == 1) {
        out[start] = (float)(g_pad[rbase + 1] & M21);
        return;
    }

    if (cnt <= ROW_DATA) {
        // q0 = (cnt_word, d0, d1, d2), q1 = (d3..d6), q2 = (d7..d10), q3 = (d11..d14)
        uint4 q0 = row[0];
        uint4 q1 = (cnt > 3)  ? row[1] : make_uint4(SENT, SENT, SENT, SENT);
        uint4 q2 = (cnt > 7)  ? row[2] : make_uint4(SENT, SENT, SENT, SENT);
        uint4 q3 = (cnt > 11) ? row[3] : make_uint4(SENT, SENT, SENT, SENT);

        unsigned int v[16] = {q0.y, q0.z, q0.w,
                              q1.x, q1.y, q1.z, q1.w,
                              q2.x, q2.y, q2.z, q2.w,
                              q3.x, q3.y, q3.z, q3.w,
                              SENT};
        #pragma unroll
        for (int j = 0; j < 15; j++)
            if (j >= cnt) v[j] = SENT;

        // Batcher odd-even mergesort network, 16 inputs (static indices)
        #pragma unroll
        for (int p = 1; p < 16; p <<= 1) {
            #pragma unroll
            for (int k = p; k >= 1; k >>= 1) {
                #pragma unroll
                for (int j = k & (p - 1); j + k < 16; j += 2 * k) {
                    #pragma unroll
                    for (int q = 0; q < k; q++) {
                        int a = j + q, b2 = j + q + k;
                        if (b2 < 16 && (a / (2 * p)) == (b2 / (2 * p)))
                            CE(a, b2);
                    }
                }
            }
        }

        #pragma unroll
        for (int j = 0; j < 15; j++)
            if (j < cnt) out[start + j] = (float)(v[j] & M21);
    } else {
        // rare overflow window: 15 row slots + overflow list
        unsigned int v[WTIER2];
        int m = 0;
        for (int j = 0; j < ROW_DATA; j++) v[m++] = g_pad[rbase + 1 + j];
        unsigned int oc = g_ovf_cnt;
        if (oc > OVF_CAP) oc = OVF_CAP;
        for (unsigned int o = 0; o < oc && m < WTIER2; o++) {
            uint2 e = g_ovf[o];
            if (e.x == (unsigned int)w) v[m++] = e.y;
        }
        for (int j = 1; j < m; j++) {
            unsigned int key = v[j];
            int k = j - 1;
            while (k >= 0 && v[k] > key) { v[k + 1] = v[k]; k--; }
            v[k + 1] = key;
        }
        for (int j = 0; j < m; j++)
            out[start + j] = (float)(v[j] & M21);
    }
}

// --- Kernel 5: flat2win + win2flat from batch tables (no coords) ------------
__global__ void final_maps_kernel(int n, int n_p,
                                  float* __restrict__ f2w,
                                  float* __restrict__ win2flat) {
    int k = blockIdx.x * blockDim.x + threadIdx.x;
    if (k == 0) g_ovf_cnt = 0;                 // reset for next graph replay

    int nb = g_nb;

    if (k < n_p) {
        int b = 0;
        #pragma unroll 1
        for (int j = 1; j < nb; j++) {
            if (g_bsp[j] <= k) b = j; else break;
        }
        int bias = g_bias[b];
        int num  = g_num[b];
        int nump = g_nump[b];
        int bspb = g_bsp[b];

        bool in_tail = (num != nump) && (k >= bspb + num);
        int val;
        if (in_tail) {
            if (nump != GROUPSZ) {
                val = k - GROUPSZ - bias;
            } else {
                int m = num > 1 ? num : 1;
                val = g_bs[b] + (k - bspb - num) % m;
            }
        } else {
            val = k - bias;
        }
        f2w[k] = (float)val;
    }

    if (k < n) {
        int b = 0;
        #pragma unroll 1
        for (int j = 1; j < nb; j++) {
            if (g_bs[j] <= k) b = j; else break;
        }
        win2flat[k] = (float)(k + g_bias[b]);
    }
}

extern "C" void kernel_launch(void* const* d_in, const int* in_sizes, int n_in,
                              void* d_out, int out_size) {
    int ci = 0;
    for (int i = 1; i < n_in; i++)
        if (in_sizes[i] > in_sizes[ci]) ci = i;

    const int* coords = (const int*)d_in[ci];
    int n = in_sizes[ci] / 4;
    if (n < 1) n = 1;
    if (n > NMAX) n = NMAX;

    const int* bsz = nullptr;
    for (int i = 0; i < n_in; i++) {
        if (i == ci) continue;
        if (in_sizes[i] == 1 && !bsz) bsz = (const int*)d_in[i];
    }

    float* out = (float*)d_out;

    bool concat = (out_size >= 3 * n);
    int n_p = concat ? (out_size - 3 * n) : out_size;
    if (n_p < 0) n_p = 0;
    if (n_p > out_size) n_p = out_size;

    int blocks = (n + 255) / 256;

    if (!concat) {
        // single-output mode: batch_setup only (ns=0 -> no pad writes), then maps
        scatter_kernel<<<blocks, 256>>>(coords, n, 0, bsz);
        int blocks_p = (n_p + 255) / 256;
        if (blocks_p >= 1)
            final_maps_kernel<<<blocks_p, 256>>>(0, n_p, out, out);
        return;
    }

    float* w2f  = out + n_p;
    float* idxx = out + n_p + n;   // idx_x ++ idx_y contiguous (2n floats)

    scatter_kernel<<<blocks, 256>>>(coords, n, n, bsz);
    scan_local_kernel<<<NTILES, S1_BLOCK>>>();
    scan_tiles_kernel<<<1, NTILES>>>();
    window_sort_kernel<<<NBINS / 256, 256>>>(idxx, 2 * n);

    int m = (n_p > n) ? n_p : n;
    int blocks_m = (m + 255) / 256;
    final_maps_kernel<<<blocks_m, 256>>>(n, n_p, out, w2f);
}

// round 17
// speedup vs baseline: 1.7606x; 1.7606x over previous
#include <cuda_runtime.h>
#include <cuda_bf16.h>

// ---------------------------------------------------------------------------
// FlattenedWindowMapping (outputs compared as float32)
// Layout: concat [flat2win[n_p] | win2flat[n] | idx_x[n] | idx_y[n]]
//
// Counting sort over (flag, batch, window) buckets (2^19 bins).
//   bin_x = b<<14 | wcx<<8 | wcy<<2 | wcz
//   bin_y = 1<<18 | b<<14 | wcy<<8 | wcx<<2 | wcz
//   key   = bin_x<<11 | cwx   (contains ALL coordinate fields)
//   element = ciw<<21 | i     (ciw 11 bits, i < 2^21)
//
// Pipeline (5 launches)  [R13 architecture, g_keyy eliminated]:
//  1. hist_rank : coords -> keyx (cached) + packed atomic ranks.
//                 Block 0 piggybacks batch_setup.
//  2. scan_local: per-tile local exclusive scan of hist (+ self-zero).
//  3. scan_tiles: one block scans 1024 tile totals.
//  4. fused_emit: f2w + w2f + atomic-free scatter; by/cwy recomputed from kx.
//  5. window_sort: register Batcher-16 on compact g_binned -> float idx out.
// ---------------------------------------------------------------------------

#define MAXB  16
#define NMAX  2000000            // < 2^21 - 1
#define NMAX2 (2 * NMAX)
#define NBINS (1 << 19)
#define GROUPSZ 128

#define S1_BLOCK 128
#define S1_ITEMS 4
#define SCAN_TILE  (S1_BLOCK * S1_ITEMS)          // 512
#define NTILES     (NBINS / SCAN_TILE)            // 1024
#define TILE_SHIFT 9

__device__ int g_nb;
__device__ int g_bs[MAXB + 1];
__device__ int g_num[MAXB];
__device__ int g_nump[MAXB];
__device__ int g_bsp[MAXB + 1];
__device__ int g_bias[MAXB];

__device__ __align__(16) unsigned int g_hist[NBINS];
__device__ __align__(16) unsigned int g_offs[NBINS];
__device__ unsigned int g_tilesum[NTILES];
__device__ unsigned int g_tilebase[NTILES];
__device__ unsigned int g_binned[NMAX2];
__device__ unsigned int g_keyx[NMAX];   // bin_x<<11 | cwx
__device__ unsigned int g_rank[NMAX];   // rx | ry<<16

// --- Kernel 1: key + histogram ranks (blk 0 piggybacks batch_setup) ---------
__global__ void hist_rank_kernel(const int* __restrict__ coords, int n,
                                 const int* __restrict__ bsz_ptr) {
    if (blockIdx.x == 0) {
        __shared__ int nb_s;
        int t = threadIdx.x;
        if (t == 0) {
            int nb = bsz_ptr ? bsz_ptr[0] : 16;
            if (nb < 1) nb = 1;
            if (nb > MAXB) nb = MAXB;
            nb_s = nb;
            g_nb = nb;
        }
        __syncthreads();
        int nb = nb_s;
        if (t <= nb) {
            int lo = 0, hi = n;
            while (lo < hi) {
                int mid = (lo + hi) >> 1;
                if (coords[4 * mid] < t) lo = mid + 1; else hi = mid;
            }
            g_bs[t] = lo;
        }
        __syncthreads();
        if (t == 0) {
            int acc = 0;
            for (int b = 0; b < nb; b++) {
                int num  = g_bs[b + 1] - g_bs[b];
                int nump = ((num + GROUPSZ - 1) / GROUPSZ) * GROUPSZ;
                g_num[b]  = num;
                g_nump[b] = nump;
                g_bsp[b]  = acc;
                g_bias[b] = acc - g_bs[b];
                acc += nump;
            }
            g_bsp[nb] = acc;
        }
    }

    int i = blockIdx.x * blockDim.x + threadIdx.x;
    if (i >= n) return;

    int4 c = reinterpret_cast<const int4*>(coords)[i];  // (b, z, y, x)
    unsigned int b = (unsigned int)c.x & 15u;
    unsigned int wcx = (unsigned int)(c.w >> 4), cix = (unsigned int)(c.w & 15);
    unsigned int wcy = (unsigned int)(c.z >> 4), ciy = (unsigned int)(c.z & 15);
    unsigned int wcz = (unsigned int)(c.y >> 3), ciz = (unsigned int)(c.y & 7);

    unsigned int bx = (b << 14) | (wcx << 8) | (wcy << 2) | wcz;
    unsigned int by = (1u << 18) | (b << 14) | (wcy << 8) | (wcx << 2) | wcz;

    unsigned int cwx = (cix << 7) | (ciy << 3) | ciz;

    unsigned int rx = atomicAdd(&g_hist[bx], 1u);
    unsigned int ry = atomicAdd(&g_hist[by], 1u);

    g_keyx[i] = (bx << 11) | cwx;
    g_rank[i] = (rx & 0xFFFFu) | (ry << 16);
}

// --- Kernel 2: per-tile local exclusive scan + hist self-zeroing ------------
__global__ void __launch_bounds__(S1_BLOCK)
scan_local_kernel() {
    __shared__ unsigned int s_warp[S1_BLOCK / 32];

    int tile = blockIdx.x;
    int t    = threadIdx.x;
    int wid  = t >> 5;
    int lane = t & 31;

    unsigned int base = (unsigned int)tile * SCAN_TILE
                      + (unsigned int)t * S1_ITEMS;

    uint4 a = *reinterpret_cast<uint4*>(&g_hist[base]);
    *reinterpret_cast<uint4*>(&g_hist[base]) = make_uint4(0, 0, 0, 0); // replay

    unsigned int v0 = a.x, v1 = a.y, v2 = a.z, v3 = a.w;
    unsigned int T = v0 + v1 + v2 + v3;

    unsigned int inc = T;
    #pragma unroll
    for (int o = 1; o < 32; o <<= 1) {
        unsigned int u = __shfl_up_sync(0xffffffffu, inc, o);
        if (lane >= o) inc += u;
    }
    if (lane == 31) s_warp[wid] = inc;
    unsigned int thread_excl = inc - T;
    __syncthreads();

    if (wid == 0) {
        unsigned int w  = (lane < (S1_BLOCK / 32)) ? s_warp[lane] : 0u;
        unsigned int wi = w;
        #pragma unroll
        for (int o = 1; o < (S1_BLOCK / 32); o <<= 1) {
            unsigned int u = __shfl_up_sync(0xffffffffu, wi, o);
            if (lane >= o) wi += u;
        }
        if (lane < (S1_BLOCK / 32)) s_warp[lane] = wi - w;
        if (lane == (S1_BLOCK / 32) - 1) g_tilesum[tile] = wi;
    }
    __syncthreads();

    unsigned int off = s_warp[wid] + thread_excl;
    uint4 o1;
    o1.x = off;  off += v0;
    o1.y = off;  off += v1;
    o1.z = off;  off += v2;
    o1.w = off;
    *reinterpret_cast<uint4*>(&g_offs[base]) = o1;
}

// --- Kernel 3: single-block exclusive scan of 1024 tile totals --------------
__global__ void __launch_bounds__(NTILES)
scan_tiles_kernel() {
    __shared__ unsigned int s_warp[NTILES / 32];

    int t    = threadIdx.x;
    int wid  = t >> 5;
    int lane = t & 31;

    unsigned int T = g_tilesum[t];
    unsigned int inc = T;
    #pragma unroll
    for (int o = 1; o < 32; o <<= 1) {
        unsigned int u = __shfl_up_sync(0xffffffffu, inc, o);
        if (lane >= o) inc += u;
    }
    if (lane == 31) s_warp[wid] = inc;
    __syncthreads();

    if (wid == 0) {
        unsigned int w  = s_warp[lane];
        unsigned int wi = w;
        #pragma unroll
        for (int o = 1; o < 32; o <<= 1) {
            unsigned int u = __shfl_up_sync(0xffffffffu, wi, o);
            if (lane >= o) wi += u;
        }
        s_warp[lane] = wi - w;
    }
    __syncthreads();

    g_tilebase[t] = s_warp[wid] + (inc - T);
}

// --- Kernel 4: f2w + w2f + atomic-free scatter (by/cwy recomputed) ----------
__global__ void fused_emit_kernel(int n, int n_p,
                                  float* __restrict__ f2w,
                                  float* __restrict__ win2flat) {
    int k = blockIdx.x * blockDim.x + threadIdx.x;

    if (k < n_p) {
        int nb = g_nb;
        int b = 0;
        #pragma unroll 1
        for (int j = 1; j < nb; j++) {
            if (g_bsp[j] <= k) b = j; else break;
        }
        int bias = g_bias[b];
        int num  = g_num[b];
        int nump = g_nump[b];
        int bspb = g_bsp[b];

        bool in_tail = (num != nump) && (k >= bspb + num);
        int val;
        if (in_tail) {
            if (nump != GROUPSZ) {
                val = k - GROUPSZ - bias;
            } else {
                int m = num > 1 ? num : 1;
                val = g_bs[b] + (k - bspb - num) % m;
            }
        } else {
            val = k - bias;
        }
        f2w[k] = (float)val;
    }

    if (k < n) {
        unsigned int kx = g_keyx[k];
        unsigned int r  = g_rank[k];

        unsigned int bx  = kx >> 11;
        unsigned int cwx = kx & 0x7FFu;

        // unpack all fields from kx
        unsigned int cix = cwx >> 7;
        unsigned int ciy = (cwx >> 3) & 15u;
        unsigned int ciz = cwx & 7u;
        unsigned int wcz = bx & 3u;
        unsigned int wcy = (bx >> 2) & 63u;
        unsigned int wcx = (bx >> 8) & 63u;
        unsigned int b   = (bx >> 14) & 15u;

        unsigned int by  = (1u << 18) | (b << 14) | (wcy << 8) | (wcx << 2) | wcz;
        unsigned int cwy = (ciy << 7) | (cix << 3) | ciz;

        win2flat[k] = (float)(k + g_bias[b]);

        unsigned int px = g_offs[bx] + g_tilebase[bx >> TILE_SHIFT]
                        + (r & 0xFFFFu);
        g_binned[px] = (cwx << 21) | (unsigned int)k;
        unsigned int py = g_offs[by] + g_tilebase[by >> TILE_SHIFT]
                        + (r >> 16);
        g_binned[py] = (cwy << 21) | (unsigned int)k;
    }
}

// --- Kernel 5: per-window register Batcher-16 sort (spill-free) -------------
#define CE(a, b) { unsigned int lo = umin(v[a], v[b]); \
                   unsigned int hi = umax(v[a], v[b]); \
                   v[a] = lo; v[b] = hi; }

#define WTIER2 64
__global__ void __launch_bounds__(256, 2)
window_sort_kernel(float* __restrict__ out, int total) {
    int w = blockIdx.x * blockDim.x + threadIdx.x;
    if (w >= NBINS) return;

    unsigned int start = g_offs[w] + g_tilebase[w >> TILE_SHIFT];
    unsigned int end   = (w == NBINS - 1)
        ? (unsigned int)total
        : g_offs[w + 1] + g_tilebase[(w + 1) >> TILE_SHIFT];
    int cnt = (int)(end - start);
    if (cnt <= 0) return;

    const unsigned int M21  = (1u << 21) - 1u;
    const unsigned int SENT = 0xFFFFFFFFu;

    if (cnt == 1) {
        out[start] = (float)(g_binned[start] & M21);
        return;
    }

    if (cnt <= 16) {
        unsigned int v[16];
        #pragma unroll
        for (int j = 0; j < 16; j++)
            v[j] = (j < cnt) ? g_binned[start + j] : SENT;

        #pragma unroll
        for (int p = 1; p < 16; p <<= 1) {
            #pragma unroll
            for (int k = p; k >= 1; k >>= 1) {
                #pragma unroll
                for (int j = k & (p - 1); j + k < 16; j += 2 * k) {
                    #pragma unroll
                    for (int q = 0; q < k; q++) {
                        int a = j + q, b2 = j + q + k;
                        if (b2 < 16 && (a / (2 * p)) == (b2 / (2 * p)))
                            CE(a, b2);
                    }
                }
            }
        }

        #pragma unroll
        for (int j = 0; j < 16; j++)
            if (j < cnt) out[start + j] = (float)(v[j] & M21);
    } else {
        int m = (cnt < WTIER2) ? cnt : WTIER2;
        for (int a = 0; a < m; a++) {
            unsigned int va = g_binned[start + a];
            int r = 0;
            for (int q = 0; q < m; q++)
                r += (g_binned[start + q] < va);
            out[start + r] = (float)(va & M21);
        }
    }
}

extern "C" void kernel_launch(void* const* d_in, const int* in_sizes, int n_in,
                              void* d_out, int out_size) {
    int ci = 0;
    for (int i = 1; i < n_in; i++)
        if (in_sizes[i] > in_sizes[ci]) ci = i;

    const int* coords = (const int*)d_in[ci];
    int n = in_sizes[ci] / 4;
    if (n < 1) n = 1;
    if (n > NMAX) n = NMAX;

    const int* bsz = nullptr;
    for (int i = 0; i < n_in; i++) {
        if (i == ci) continue;
        if (in_sizes[i] == 1 && !bsz) bsz = (const int*)d_in[i];
    }

    float* out = (float*)d_out;

    bool concat = (out_size >= 3 * n);
    int n_p = concat ? (out_size - 3 * n) : out_size;
    if (n_p < 0) n_p = 0;
    if (n_p > out_size) n_p = out_size;

    int blocks = (n + 255) / 256;

    if (!concat) {
        hist_rank_kernel<<<blocks, 256>>>(coords, n, bsz);
        scan_local_kernel<<<NTILES, S1_BLOCK>>>();    // scrub counters
        int blocks_p = (n_p + 255) / 256;
        if (blocks_p >= 1)
            fused_emit_kernel<<<blocks_p, 256>>>(0, n_p, out, out);
        return;
    }

    float* w2f  = out + n_p;
    float* idxx = out + n_p + n;   // idx_x ++ idx_y contiguous (2n floats)

    hist_rank_kernel<<<blocks, 256>>>(coords, n, bsz);
    scan_local_kernel<<<NTILES, S1_BLOCK>>>();
    scan_tiles_kernel<<<1, NTILES>>>();

    int m = (n_p > n) ? n_p : n;
    int blocks_m = (m + 255) / 256;
    fused_emit_kernel<<<blocks_m, 256>>>(n, n_p, out, w2f);

    window_sort_kernel<<<NBINS / 256, 256>>>(idxx, 2 * n);
}